// round 1
// baseline (speedup 1.0000x reference)
#include <cuda_runtime.h>
#include <math_constants.h>

// Erosion2d: 3x3 min-pool, stride 1, pad value 1e9 (acts as +INF identity).
// x: [16, 64, 256, 256] f32  ->  out same shape.
// Each thread computes 4 contiguous output columns via float4 loads/stores.

#define H 256
#define W 256
#define W4 64          // W / 4 column-groups per row
#define NIMG 1024      // 16 * 64 planes

__global__ void __launch_bounds__(256, 8)
erosion3x3_kernel(const float* __restrict__ x, float* __restrict__ out) {
    int tid = blockIdx.x * blockDim.x + threadIdx.x;
    // tid -> (img, row, colgroup)
    int cg  = tid & (W4 - 1);
    int row = (tid >> 6) & (H - 1);
    int img = tid >> 14;

    const size_t base = ((size_t)img << 16) + ((size_t)row << 8) + ((size_t)cg << 2);
    const float* p = x + base;

    float4 v = make_float4(CUDART_INF_F, CUDART_INF_F, CUDART_INF_F, CUDART_INF_F);
    float l = CUDART_INF_F;
    float r = CUDART_INF_F;

    const bool has_l = (cg != 0);
    const bool has_r = (cg != W4 - 1);

    #pragma unroll
    for (int dr = -1; dr <= 1; dr++) {
        int rr = row + dr;
        if ((unsigned)rr < (unsigned)H) {
            const float* q = p + dr * W;
            float4 t = *reinterpret_cast<const float4*>(q);
            v.x = fminf(v.x, t.x);
            v.y = fminf(v.y, t.y);
            v.z = fminf(v.z, t.z);
            v.w = fminf(v.w, t.w);
            if (has_l) l = fminf(l, q[-1]);
            if (has_r) r = fminf(r, q[4]);
        }
    }

    float4 o;
    o.x = fminf(l,   fminf(v.x, v.y));
    o.y = fminf(v.x, fminf(v.y, v.z));
    o.z = fminf(v.y, fminf(v.z, v.w));
    o.w = fminf(v.z, fminf(v.w, r));

    *reinterpret_cast<float4*>(out + base) = o;
}

extern "C" void kernel_launch(void* const* d_in, const int* in_sizes, int n_in,
                              void* d_out, int out_size) {
    const float* x = (const float*)d_in[0];
    float* out = (float*)d_out;
    // total threads = NIMG * H * W4 = 1024*256*64 = 16,777,216
    const int threads = 256;
    const int blocks  = (NIMG * H * W4) / threads;  // 65536
    erosion3x3_kernel<<<blocks, threads>>>(x, out);
}

// round 2
// speedup vs baseline: 1.2913x; 1.2913x over previous
#include <cuda_runtime.h>
#include <math_constants.h>

// Erosion2d: 3x3 min-pool, stride 1, +1e9 pad == +INF identity.
// x: [16,64,256,256] f32 -> out same shape.
//
// One warp covers the full W=256 of R=4 consecutive rows:
//   lane l holds cols [8l, 8l+7] as 2x float4.
// Vertical min via register sliding window over R+2 rows.
// Horizontal halo via warp shuffle of the vertical-min vector
// (left neighbor's elem7 / right neighbor's elem0) -> no scalar loads.

#define H 256
#define W4 64          // row width in float4 units
#define R 4            // output rows per warp
#define TILES (H / R)  // 64 row-tiles per plane
#define NIMG 1024      // 16*64 planes

__device__ __forceinline__ float min3f(float a, float b, float c) {
    return fminf(fminf(a, b), c);
}
__device__ __forceinline__ float4 min3v(const float4& a, const float4& b, const float4& c) {
    return make_float4(min3f(a.x, b.x, c.x), min3f(a.y, b.y, c.y),
                       min3f(a.z, b.z, c.z), min3f(a.w, b.w, c.w));
}

__global__ void __launch_bounds__(256)
erosion3x3_warp_kernel(const float4* __restrict__ x, float4* __restrict__ out) {
    const int gwarp = (blockIdx.x * blockDim.x + threadIdx.x) >> 5;
    const int lane  = threadIdx.x & 31;

    const int tile = gwarp & (TILES - 1);
    const int img  = gwarp >> 6;          // gwarp / TILES
    const int row0 = tile * R;

    // base (float4 units): img*H*W4 + row0*W4 + lane*2
    const size_t base = ((size_t)img << 14) + ((size_t)row0 << 6) + ((size_t)lane << 1);
    const float4* p = x + base;
    float4* po = out + base;

    const float4 INF4 = make_float4(CUDART_INF_F, CUDART_INF_F, CUDART_INF_F, CUDART_INF_F);

    // sliding window of 3 input rows, 2x float4 each
    float4 w[3][2];

    // load rows row0-1 and row0
    {
        if (row0 > 0) {
            w[0][0] = p[-W4]; w[0][1] = p[-W4 + 1];
        } else {
            w[0][0] = INF4;   w[0][1] = INF4;
        }
        w[1][0] = p[0]; w[1][1] = p[1];
    }

    #pragma unroll
    for (int i = 0; i < R; i++) {
        const int rr = row0 + i + 1;           // next input row
        const int s0 = i % 3, s1 = (i + 1) % 3, s2 = (i + 2) % 3;
        if (rr < H) {
            const float4* q = p + (size_t)(i + 1) * W4;
            w[s2][0] = q[0]; w[s2][1] = q[1];
        } else {
            w[s2][0] = INF4; w[s2][1] = INF4;
        }

        // vertical min over the 3 window rows
        float4 v0 = min3v(w[s0][0], w[s1][0], w[s2][0]);
        float4 v1 = min3v(w[s0][1], w[s1][1], w[s2][1]);

        // horizontal halos via shuffle of vertical-min vector
        float l = __shfl_up_sync(0xffffffffu, v1.w, 1);    // left neighbor col 8l-1
        float r = __shfl_down_sync(0xffffffffu, v0.x, 1);  // right neighbor col 8l+8
        if (lane == 0)  l = CUDART_INF_F;
        if (lane == 31) r = CUDART_INF_F;

        float4 o0, o1;
        o0.x = min3f(l,    v0.x, v0.y);
        o0.y = min3f(v0.x, v0.y, v0.z);
        o0.z = min3f(v0.y, v0.z, v0.w);
        o0.w = min3f(v0.z, v0.w, v1.x);
        o1.x = min3f(v0.w, v1.x, v1.y);
        o1.y = min3f(v1.x, v1.y, v1.z);
        o1.z = min3f(v1.y, v1.z, v1.w);
        o1.w = min3f(v1.z, v1.w, r);

        float4* qo = po + (size_t)i * W4;
        qo[0] = o0; qo[1] = o1;
    }
}

extern "C" void kernel_launch(void* const* d_in, const int* in_sizes, int n_in,
                              void* d_out, int out_size) {
    const float4* x = (const float4*)d_in[0];
    float4* out = (float4*)d_out;
    // warps = NIMG * TILES = 1024*64 = 65536; 8 warps/block -> 8192 blocks
    const int threads = 256;
    const int blocks  = (NIMG * TILES * 32) / threads;
    erosion3x3_warp_kernel<<<blocks, threads>>>(x, out);
}